// round 10
// baseline (speedup 1.0000x reference)
#include <cuda_runtime.h>
#include <math.h>

#define B_ 4
#define I_ 512
#define K_ 512
#define C_ 64
#define EPS_LN 1e-5f

// -------- scratch (device globals; allocation is forbidden) --------
__device__ float   g_Qa[B_ * K_ * C_];      // Q @ W1^T + b1
__device__ float   g_R [B_ * K_ * C_];      // Qa / D
__device__ float   g_Va[B_ * I_ * C_];      // contraction result (pre-LN1)
__device__ float   g_Vp[B_ * I_ * C_];      // V + LN1(Va)@W2^T + b2 (pre-LN2)
__device__ double2 g_part1[B_ * I_];        // per-(b,i) {sum,sumsq} of Va
__device__ double2 g_part2[(B_ * I_) / 4];  // per-linear2-block {sum,sumsq}
__device__ float   g_mean1[B_], g_rstd1[B_];
__device__ float   g_mean2[B_], g_rstd2[B_];
__device__ unsigned g_cnt1;                 // zero-init; reset by last block
__device__ unsigned g_cnt2;

// ---------------------------------------------------------------
// Kernel 1: Qa[b,k,c] = b1[c] + sum_j Q[b,k,j] * W1[c,j]   (R2-proven)
// ---------------------------------------------------------------
__global__ void k_linear1(const float* __restrict__ Q,
                          const float* __restrict__ W1,
                          const float* __restrict__ b1) {
    __shared__ float Ws[C_][C_ + 1];
    __shared__ float Qs[4][C_];
    int t = threadIdx.x;
    for (int idx = t; idx < C_ * C_; idx += 256)
        Ws[idx / C_][idx % C_] = W1[idx];
    int r = t >> 6, c = t & 63;
    int grow = blockIdx.x * 4 + r;
    Qs[r][c] = Q[(size_t)grow * C_ + c];
    __syncthreads();
    float acc = b1[c];
#pragma unroll
    for (int j = 0; j < C_; j++)
        acc += Qs[r][j] * Ws[c][j];
    g_Qa[(size_t)grow * C_ + c] = acc;
}

// ---------------------------------------------------------------
// Deterministic active-index compaction (R2-proven form).
//   WMODE 0 : weight = m + 1e-6            [pass1]
//   WMODE 1 : weight = m * (m + 1e-6)      [pass2]
// ---------------------------------------------------------------
template<int WMODE>
__device__ __forceinline__ int compact_active(const float* __restrict__ mp,
                                              size_t mstride,
                                              int* s_idx, float* s_w,
                                              int* s_cnt, int* s_off) {
    int t = threadIdx.x;
    int lane = t & 31, wid = t >> 5;
    float mv[2]; unsigned bal[2];
#pragma unroll
    for (int q = 0; q < 2; q++) {
        int g = wid + q * 8;
        int i = g * 32 + lane;
        mv[q] = __ldg(&mp[(size_t)i * mstride]);
        bal[q] = __ballot_sync(0xffffffffu, mv[q] != 0.f);
        if (lane == 0) s_cnt[g] = __popc(bal[q]);
    }
    __syncthreads();
    if (t == 0) {
        int acc = 0;
#pragma unroll
        for (int g = 0; g < 16; g++) { s_off[g] = acc; acc += s_cnt[g]; }
        s_off[16] = acc;
    }
    __syncthreads();
#pragma unroll
    for (int q = 0; q < 2; q++) {
        int g = wid + q * 8;
        int i = g * 32 + lane;
        if (mv[q] != 0.f) {
            int pos = s_off[g] + __popc(bal[q] & ((1u << lane) - 1u));
            s_idx[pos] = i;
            s_w[pos] = (WMODE == 0) ? (mv[q] + 1e-6f)
                                    : (mv[q] * (mv[q] + 1e-6f));
        }
    }
    __syncthreads();
    return s_off[16];
}

// ---------------------------------------------------------------
// Pass 1 (R9-proven): per (b,k):
//   D[c] = sum_{active i} exp(z[b,i,k,c]) * (m+1e-6)
//   R[b,k,c] = Qa[b,k,c] / D[c]
// ---------------------------------------------------------------
__global__ void __launch_bounds__(256, 8)
k_pass1(const float* __restrict__ z, const float* __restrict__ zm) {
    int k = blockIdx.x, b = blockIdx.y;
    int t = threadIdx.x;
    __shared__ int    s_idx[I_];
    __shared__ float  s_w[I_];
    __shared__ int    s_cnt[16];
    __shared__ int    s_off[17];
    __shared__ float4 red[16][16];

    const float* mp = zm + (size_t)b * I_ * K_ + k;
    int nact = compact_active<0>(mp, K_, s_idx, s_w, s_cnt, s_off);

    int c4 = t & 15;        // float4 channel group
    int di = t >> 4;        // row lane
    const float4* zb = (const float4*)z
        + (((size_t)b * I_) * K_ + k) * (C_ / 4) + c4;
    const size_t zstride = (size_t)K_ * (C_ / 4);

    float4 acc = make_float4(0.f, 0.f, 0.f, 0.f);
#pragma unroll 4
    for (int j = di; j < nact; j += 16) {
        int i = s_idx[j];
        float w = s_w[j];
        float4 zv = __ldg(&zb[(size_t)i * zstride]);
        acc.x += __expf(zv.x) * w;
        acc.y += __expf(zv.y) * w;
        acc.z += __expf(zv.z) * w;
        acc.w += __expf(zv.w) * w;
    }
    red[di][c4] = acc;
    __syncthreads();
    if (t < 16) {
        float4 D = red[0][t];
#pragma unroll
        for (int r = 1; r < 16; r++) {
            float4 v = red[r][t];
            D.x += v.x; D.y += v.y; D.z += v.z; D.w += v.w;
        }
        size_t off = ((size_t)b * K_ + k) * (C_ / 4) + t;
        float4 qa = ((const float4*)g_Qa)[off];
        float4 R = make_float4(qa.x / D.x, qa.y / D.y,
                               qa.z / D.z, qa.w / D.w);
        ((float4*)g_R)[off] = R;
    }
}

// ---------------------------------------------------------------
// Pass 2 (R9-proven body + last-block LN1 reduce): per (b,i):
//   Va[b,i,c] = sum_{active k} m*(m+1e-6) * exp(z[b,i,k,c]) * R[b,k,c]
// ---------------------------------------------------------------
__global__ void __launch_bounds__(256, 8)
k_pass2(const float* __restrict__ z, const float* __restrict__ zm) {
    int i = blockIdx.x, b = blockIdx.y;
    int t = threadIdx.x;
    __shared__ int    s_idx[K_];
    __shared__ float  s_w[K_];
    __shared__ int    s_cnt[16];
    __shared__ int    s_off[17];
    __shared__ float4 red[16][16];
    __shared__ double sd[16], sd2[16];
    __shared__ bool   isLast;

    const float* mp = zm + ((size_t)b * I_ + i) * K_;
    int nact = compact_active<1>(mp, 1, s_idx, s_w, s_cnt, s_off);

    int c4 = t & 15;
    int dk = t >> 4;
    const float4* zb = (const float4*)z
        + (((size_t)b * I_ + i) * K_) * (C_ / 4) + c4;
    const float4* Rb = (const float4*)g_R + ((size_t)b * K_) * (C_ / 4) + c4;

    float4 acc = make_float4(0.f, 0.f, 0.f, 0.f);
#pragma unroll 4
    for (int j = dk; j < nact; j += 16) {
        int kk = s_idx[j];
        float w = s_w[j];
        float4 zv = __ldg(&zb[(size_t)kk * (C_ / 4)]);
        float4 Rv = __ldg(&Rb[(size_t)kk * (C_ / 4)]);
        acc.x += w * __expf(zv.x) * Rv.x;
        acc.y += w * __expf(zv.y) * Rv.y;
        acc.z += w * __expf(zv.z) * Rv.z;
        acc.w += w * __expf(zv.w) * Rv.w;
    }
    red[dk][c4] = acc;
    __syncthreads();
    if (t < 16) {
        float4 v = red[0][t];
#pragma unroll
        for (int r = 1; r < 16; r++) {
            float4 u = red[r][t];
            v.x += u.x; v.y += u.y; v.z += u.z; v.w += u.w;
        }
        ((float4*)g_Va)[((size_t)b * I_ + i) * (C_ / 4) + t] = v;
        sd [t] = (double)v.x + (double)v.y + (double)v.z + (double)v.w;
        sd2[t] = (double)v.x * v.x + (double)v.y * v.y
               + (double)v.z * v.z + (double)v.w * v.w;
    }
    __syncthreads();
    if (t == 0) {
        double s = 0.0, s2 = 0.0;
#pragma unroll
        for (int r = 0; r < 16; r++) { s += sd[r]; s2 += sd2[r]; }
        g_part1[(size_t)b * I_ + i] = make_double2(s, s2);
        __threadfence();
        unsigned v = atomicAdd(&g_cnt1, 1u);
        isLast = (v == (unsigned)(I_ * B_ - 1));
    }
    __syncthreads();
    if (isLast) {                       // fixed-order -> deterministic
        int wid = t >> 5, lane = t & 31;
        if (wid < B_) {
            double s = 0.0, s2 = 0.0;
            for (int j = lane; j < I_; j += 32) {
                double2 p = g_part1[(size_t)wid * I_ + j];
                s += p.x; s2 += p.y;
            }
#pragma unroll
            for (int o = 16; o > 0; o >>= 1) {
                s  += __shfl_down_sync(0xffffffffu, s,  o);
                s2 += __shfl_down_sync(0xffffffffu, s2, o);
            }
            if (lane == 0) {
                const double N = (double)(I_ * C_);
                double mu  = s / N;
                double var = s2 / N - mu * mu;
                g_mean1[wid] = (float)mu;
                g_rstd1[wid] = (float)(1.0 / sqrt(var + (double)EPS_LN));
            }
        }
        if (t == 0) g_cnt1 = 0;         // reset for next graph replay
    }
}

// ---------------------------------------------------------------
// Linear2 (R9-proven body + last-block LN2 reduce):
//   Vp = V + LN1(Va)@W2^T + b2
// ---------------------------------------------------------------
__global__ void k_linear2(const float* __restrict__ V,
                          const float* __restrict__ W2,
                          const float* __restrict__ b2) {
    __shared__ float  Ws[C_][C_ + 1];
    __shared__ float  Xs[4][C_];
    __shared__ double sh0[256], sh1[256];
    __shared__ bool   isLast;
    int t = threadIdx.x;
    for (int idx = t; idx < C_ * C_; idx += 256)
        Ws[idx / C_][idx % C_] = W2[idx];
    int r = t >> 6, c = t & 63;
    int grow = blockIdx.x * 4 + r;
    int b = grow >> 9;
    float mu = g_mean1[b], rs = g_rstd1[b];
    Xs[r][c] = (g_Va[(size_t)grow * C_ + c] - mu) * rs;
    __syncthreads();
    float acc = b2[c];
#pragma unroll
    for (int j = 0; j < C_; j++)
        acc += Xs[r][j] * Ws[c][j];
    float v = V[(size_t)grow * C_ + c] + acc;
    g_Vp[(size_t)grow * C_ + c] = v;

    sh0[t] = (double)v;
    sh1[t] = (double)v * (double)v;
    __syncthreads();
    for (int o = 128; o > 0; o >>= 1) {
        if (t < o) { sh0[t] += sh0[t + o]; sh1[t] += sh1[t + o]; }
        __syncthreads();
    }
    if (t == 0) {
        g_part2[blockIdx.x] = make_double2(sh0[0], sh1[0]);
        __threadfence();
        unsigned x = atomicAdd(&g_cnt2, 1u);
        isLast = (x == (unsigned)((B_ * I_) / 4 - 1));
    }
    __syncthreads();
    if (isLast) {                       // fixed-order -> deterministic
        int wid = t >> 5, lane = t & 31;
        const int PB = I_ / 4;          // partials per batch = 128
        if (wid < B_) {
            double s = 0.0, s2 = 0.0;
            for (int j = lane; j < PB; j += 32) {
                double2 p = g_part2[(size_t)wid * PB + j];
                s += p.x; s2 += p.y;
            }
#pragma unroll
            for (int o = 16; o > 0; o >>= 1) {
                s  += __shfl_down_sync(0xffffffffu, s,  o);
                s2 += __shfl_down_sync(0xffffffffu, s2, o);
            }
            if (lane == 0) {
                const double N = (double)(I_ * C_);
                double mu  = s / N;
                double var = s2 / N - mu * mu;
                g_mean2[wid] = (float)mu;
                g_rstd2[wid] = (float)(1.0 / sqrt(var + (double)EPS_LN));
            }
        }
        if (t == 0) g_cnt2 = 0;
    }
}

// ---------------------------------------------------------------
// Final: out = (Vp - mean2[b]) * rstd2[b]
// ---------------------------------------------------------------
__global__ void k_final(float* __restrict__ out) {
    int idx = blockIdx.x * blockDim.x + threadIdx.x;
    int b = idx >> 15;
    out[idx] = (g_Vp[idx] - g_mean2[b]) * g_rstd2[b];
}

// ---------------------------------------------------------------
extern "C" void kernel_launch(void* const* d_in, const int* in_sizes, int n_in,
                              void* d_out, int out_size) {
    const float* V  = (const float*)d_in[0];
    const float* Q  = (const float*)d_in[1];
    const float* z  = (const float*)d_in[2];
    const float* zm = (const float*)d_in[3];
    const float* W1 = (const float*)d_in[4];
    const float* b1 = (const float*)d_in[5];
    const float* W2 = (const float*)d_in[6];
    const float* b2 = (const float*)d_in[7];
    float* out = (float*)d_out;

    k_linear1<<<(B_ * K_) / 4, 256>>>(Q, W1, b1);
    k_pass1  <<<dim3(K_, B_), 256>>>(z, zm);
    k_pass2  <<<dim3(I_, B_), 256>>>(z, zm);
    k_linear2<<<(B_ * I_) / 4, 256>>>(V, W2, b2);
    k_final  <<<(B_ * I_ * C_) / 256, 256>>>(out);
}

// round 11
// speedup vs baseline: 1.0346x; 1.0346x over previous
#include <cuda_runtime.h>
#include <math.h>

#define B_ 4
#define I_ 512
#define K_ 512
#define C_ 64
#define EPS_LN 1e-5f

// -------- scratch (device globals; allocation is forbidden) --------
__device__ float   g_Qa[B_ * K_ * C_];      // Q @ W1^T + b1
__device__ float   g_R [B_ * K_ * C_];      // Qa / D
__device__ float   g_Va[B_ * I_ * C_];      // contraction result (pre-LN1)
__device__ float   g_Vp[B_ * I_ * C_];      // V + LN1(Va)@W2^T + b2 (pre-LN2)
__device__ double2 g_part1[B_ * I_];        // per-(b,i) {sum,sumsq} of Va
__device__ double2 g_part2[128];            // per-linear2-block {sum,sumsq}
__device__ float   g_mean1[B_], g_rstd1[B_];
__device__ float   g_mean2[B_], g_rstd2[B_];

// ---------------------------------------------------------------
// Linear1 (16 rows/block): Qa[row,c] = b1[c] + sum_j Q[row,j]*W1[c,j]
// W1 staged ONCE per 16 rows; each thread computes 4 rows at one c,
// sharing a single Ws[c][j] read across 4 FFMAs.
// ---------------------------------------------------------------
__global__ void __launch_bounds__(256) k_linear1(const float* __restrict__ Q,
                                                 const float* __restrict__ W1,
                                                 const float* __restrict__ b1) {
    __shared__ float Ws[C_][C_ + 1];
    __shared__ float Qs[16][C_];
    int t = threadIdx.x;
    int base = blockIdx.x * 16;
    for (int idx = t; idx < C_ * C_; idx += 256)
        Ws[idx / C_][idx % C_] = W1[idx];
    for (int idx = t; idx < 16 * C_; idx += 256)
        Qs[idx >> 6][idx & 63] = Q[(size_t)(base + (idx >> 6)) * C_ + (idx & 63)];
    __syncthreads();
    int c = t & 63, rg = t >> 6;        // rg in 0..3, rows rg*4..rg*4+3
    float bb = __ldg(&b1[c]);
    float a0 = bb, a1 = bb, a2 = bb, a3 = bb;
#pragma unroll
    for (int j = 0; j < C_; j++) {
        float w = Ws[c][j];
        a0 += Qs[rg * 4 + 0][j] * w;
        a1 += Qs[rg * 4 + 1][j] * w;
        a2 += Qs[rg * 4 + 2][j] * w;
        a3 += Qs[rg * 4 + 3][j] * w;
    }
    g_Qa[(size_t)(base + rg * 4 + 0) * C_ + c] = a0;
    g_Qa[(size_t)(base + rg * 4 + 1) * C_ + c] = a1;
    g_Qa[(size_t)(base + rg * 4 + 2) * C_ + c] = a2;
    g_Qa[(size_t)(base + rg * 4 + 3) * C_ + c] = a3;
}

// ---------------------------------------------------------------
// Deterministic active-index compaction (R2-proven form).
//   WMODE 0 : weight = m + 1e-6            [pass1]
//   WMODE 1 : weight = m * (m + 1e-6)      [pass2]
// ---------------------------------------------------------------
template<int WMODE>
__device__ __forceinline__ int compact_active(const float* __restrict__ mp,
                                              size_t mstride,
                                              int* s_idx, float* s_w,
                                              int* s_cnt, int* s_off) {
    int t = threadIdx.x;
    int lane = t & 31, wid = t >> 5;
    float mv[2]; unsigned bal[2];
#pragma unroll
    for (int q = 0; q < 2; q++) {
        int g = wid + q * 8;
        int i = g * 32 + lane;
        mv[q] = __ldg(&mp[(size_t)i * mstride]);
        bal[q] = __ballot_sync(0xffffffffu, mv[q] != 0.f);
        if (lane == 0) s_cnt[g] = __popc(bal[q]);
    }
    __syncthreads();
    if (t == 0) {
        int acc = 0;
#pragma unroll
        for (int g = 0; g < 16; g++) { s_off[g] = acc; acc += s_cnt[g]; }
        s_off[16] = acc;
    }
    __syncthreads();
#pragma unroll
    for (int q = 0; q < 2; q++) {
        int g = wid + q * 8;
        int i = g * 32 + lane;
        if (mv[q] != 0.f) {
            int pos = s_off[g] + __popc(bal[q] & ((1u << lane) - 1u));
            s_idx[pos] = i;
            s_w[pos] = (WMODE == 0) ? (mv[q] + 1e-6f)
                                    : (mv[q] * (mv[q] + 1e-6f));
        }
    }
    __syncthreads();
    return s_off[16];
}

// ---------------------------------------------------------------
// Pass 1 (R9-proven): per (b,k):
//   D[c] = sum_{active i} exp(z[b,i,k,c]) * (m+1e-6)
//   R[b,k,c] = Qa[b,k,c] / D[c]
// ---------------------------------------------------------------
__global__ void __launch_bounds__(256, 8)
k_pass1(const float* __restrict__ z, const float* __restrict__ zm) {
    int k = blockIdx.x, b = blockIdx.y;
    int t = threadIdx.x;
    __shared__ int    s_idx[I_];
    __shared__ float  s_w[I_];
    __shared__ int    s_cnt[16];
    __shared__ int    s_off[17];
    __shared__ float4 red[16][16];

    const float* mp = zm + (size_t)b * I_ * K_ + k;
    int nact = compact_active<0>(mp, K_, s_idx, s_w, s_cnt, s_off);

    int c4 = t & 15;        // float4 channel group
    int di = t >> 4;        // row lane
    const float4* zb = (const float4*)z
        + (((size_t)b * I_) * K_ + k) * (C_ / 4) + c4;
    const size_t zstride = (size_t)K_ * (C_ / 4);

    float4 acc = make_float4(0.f, 0.f, 0.f, 0.f);
#pragma unroll 4
    for (int j = di; j < nact; j += 16) {
        int i = s_idx[j];
        float w = s_w[j];
        float4 zv = __ldg(&zb[(size_t)i * zstride]);
        acc.x += __expf(zv.x) * w;
        acc.y += __expf(zv.y) * w;
        acc.z += __expf(zv.z) * w;
        acc.w += __expf(zv.w) * w;
    }
    red[di][c4] = acc;
    __syncthreads();
    if (t < 16) {
        float4 D = red[0][t];
#pragma unroll
        for (int r = 1; r < 16; r++) {
            float4 v = red[r][t];
            D.x += v.x; D.y += v.y; D.z += v.z; D.w += v.w;
        }
        size_t off = ((size_t)b * K_ + k) * (C_ / 4) + t;
        float4 qa = ((const float4*)g_Qa)[off];
        float4 R = make_float4(qa.x / D.x, qa.y / D.y,
                               qa.z / D.z, qa.w / D.w);
        ((float4*)g_R)[off] = R;
    }
}

// ---------------------------------------------------------------
// Pass 2 (R9-proven): per (b,i):
//   Va[b,i,c] = sum_{active k} m*(m+1e-6) * exp(z[b,i,k,c]) * R[b,k,c]
// Emits per-row LN1 partials.
// ---------------------------------------------------------------
__global__ void __launch_bounds__(256, 8)
k_pass2(const float* __restrict__ z, const float* __restrict__ zm) {
    int i = blockIdx.x, b = blockIdx.y;
    int t = threadIdx.x;
    __shared__ int    s_idx[K_];
    __shared__ float  s_w[K_];
    __shared__ int    s_cnt[16];
    __shared__ int    s_off[17];
    __shared__ float4 red[16][16];
    __shared__ double sd[16], sd2[16];

    const float* mp = zm + ((size_t)b * I_ + i) * K_;
    int nact = compact_active<1>(mp, 1, s_idx, s_w, s_cnt, s_off);

    int c4 = t & 15;
    int dk = t >> 4;
    const float4* zb = (const float4*)z
        + (((size_t)b * I_ + i) * K_) * (C_ / 4) + c4;
    const float4* Rb = (const float4*)g_R + ((size_t)b * K_) * (C_ / 4) + c4;

    float4 acc = make_float4(0.f, 0.f, 0.f, 0.f);
#pragma unroll 4
    for (int j = dk; j < nact; j += 16) {
        int kk = s_idx[j];
        float w = s_w[j];
        float4 zv = __ldg(&zb[(size_t)kk * (C_ / 4)]);
        float4 Rv = __ldg(&Rb[(size_t)kk * (C_ / 4)]);
        acc.x += w * __expf(zv.x) * Rv.x;
        acc.y += w * __expf(zv.y) * Rv.y;
        acc.z += w * __expf(zv.z) * Rv.z;
        acc.w += w * __expf(zv.w) * Rv.w;
    }
    red[dk][c4] = acc;
    __syncthreads();
    if (t < 16) {
        float4 v = red[0][t];
#pragma unroll
        for (int r = 1; r < 16; r++) {
            float4 u = red[r][t];
            v.x += u.x; v.y += u.y; v.z += u.z; v.w += u.w;
        }
        ((float4*)g_Va)[((size_t)b * I_ + i) * (C_ / 4) + t] = v;
        sd [t] = (double)v.x + (double)v.y + (double)v.z + (double)v.w;
        sd2[t] = (double)v.x * v.x + (double)v.y * v.y
               + (double)v.z * v.z + (double)v.w * v.w;
    }
    __syncthreads();
    if (t == 0) {
        double s = 0.0, s2 = 0.0;
#pragma unroll
        for (int r = 0; r < 16; r++) { s += sd[r]; s2 += sd2[r]; }
        g_part1[(size_t)b * I_ + i] = make_double2(s, s2);
    }
}

// ---------------------------------------------------------------
// Tiny stats reduce: partials -> per-batch mean/rstd.
// which==0: g_part1, 512/batch.  which==1: g_part2, 32/batch.
// ---------------------------------------------------------------
__global__ void k_reduce(int which) {
    int b = blockIdx.x;
    int n = (which == 0) ? I_ : 32;
    const double2* p = (which == 0 ? g_part1 : g_part2) + (size_t)b * n;
    double s = 0.0, s2 = 0.0;
    for (int j = threadIdx.x; j < n; j += 256) {
        double2 v = p[j];
        s += v.x; s2 += v.y;
    }
    __shared__ double sh0[256], sh1[256];
    sh0[threadIdx.x] = s; sh1[threadIdx.x] = s2;
    __syncthreads();
    for (int o = 128; o > 0; o >>= 1) {
        if (threadIdx.x < o) {
            sh0[threadIdx.x] += sh0[threadIdx.x + o];
            sh1[threadIdx.x] += sh1[threadIdx.x + o];
        }
        __syncthreads();
    }
    if (threadIdx.x == 0) {
        const double N = (double)(I_ * C_);
        double mu  = sh0[0] / N;
        double var = sh1[0] / N - mu * mu;
        float rstd = (float)(1.0 / sqrt(var + (double)EPS_LN));
        if (which == 0) { g_mean1[b] = (float)mu; g_rstd1[b] = rstd; }
        else            { g_mean2[b] = (float)mu; g_rstd2[b] = rstd; }
    }
}

// ---------------------------------------------------------------
// Linear2 (16 rows/block): Vp = V + LN1(Va)@W2^T + b2.
// W2 staged once per 16 rows; 4 outputs/thread; LN2 partials via
// warp shuffle (fixed order -> deterministic).
// ---------------------------------------------------------------
__global__ void __launch_bounds__(256) k_linear2(const float* __restrict__ V,
                                                 const float* __restrict__ W2,
                                                 const float* __restrict__ b2) {
    __shared__ float  Ws[C_][C_ + 1];
    __shared__ float  Xs[16][C_];
    __shared__ double swp[8][2];
    int t = threadIdx.x;
    int base = blockIdx.x * 16;
    int b = blockIdx.x >> 5;            // 32 blocks per batch
    float mu = g_mean1[b], rs = g_rstd1[b];
    for (int idx = t; idx < C_ * C_; idx += 256)
        Ws[idx / C_][idx % C_] = W2[idx];
    for (int idx = t; idx < 16 * C_; idx += 256)
        Xs[idx >> 6][idx & 63] =
            (g_Va[(size_t)(base + (idx >> 6)) * C_ + (idx & 63)] - mu) * rs;
    __syncthreads();
    int c = t & 63, rg = t >> 6;
    float bb = __ldg(&b2[c]);
    float a0 = bb, a1 = bb, a2 = bb, a3 = bb;
#pragma unroll
    for (int j = 0; j < C_; j++) {
        float w = Ws[c][j];
        a0 += Xs[rg * 4 + 0][j] * w;
        a1 += Xs[rg * 4 + 1][j] * w;
        a2 += Xs[rg * 4 + 2][j] * w;
        a3 += Xs[rg * 4 + 3][j] * w;
    }
    double s = 0.0, s2 = 0.0;
    float av[4] = {a0, a1, a2, a3};
#pragma unroll
    for (int q = 0; q < 4; q++) {
        size_t off = (size_t)(base + rg * 4 + q) * C_ + c;
        float v = __ldg(&V[off]) + av[q];
        g_Vp[off] = v;
        s  += (double)v;
        s2 += (double)v * (double)v;
    }
#pragma unroll
    for (int o = 16; o > 0; o >>= 1) {
        s  += __shfl_down_sync(0xffffffffu, s,  o);
        s2 += __shfl_down_sync(0xffffffffu, s2, o);
    }
    int lane = t & 31, wid = t >> 5;
    if (lane == 0) { swp[wid][0] = s; swp[wid][1] = s2; }
    __syncthreads();
    if (t == 0) {
        double ts = 0.0, ts2 = 0.0;
#pragma unroll
        for (int w = 0; w < 8; w++) { ts += swp[w][0]; ts2 += swp[w][1]; }
        g_part2[blockIdx.x] = make_double2(ts, ts2);
    }
}

// ---------------------------------------------------------------
// Final: out = (Vp - mean2[b]) * rstd2[b]
// ---------------------------------------------------------------
__global__ void k_final(float* __restrict__ out) {
    int idx = blockIdx.x * blockDim.x + threadIdx.x;
    int b = idx >> 15;
    out[idx] = (g_Vp[idx] - g_mean2[b]) * g_rstd2[b];
}

// ---------------------------------------------------------------
extern "C" void kernel_launch(void* const* d_in, const int* in_sizes, int n_in,
                              void* d_out, int out_size) {
    const float* V  = (const float*)d_in[0];
    const float* Q  = (const float*)d_in[1];
    const float* z  = (const float*)d_in[2];
    const float* zm = (const float*)d_in[3];
    const float* W1 = (const float*)d_in[4];
    const float* b1 = (const float*)d_in[5];
    const float* W2 = (const float*)d_in[6];
    const float* b2 = (const float*)d_in[7];
    float* out = (float*)d_out;

    k_linear1<<<(B_ * K_) / 16, 256>>>(Q, W1, b1);
    k_pass1  <<<dim3(K_, B_), 256>>>(z, zm);
    k_pass2  <<<dim3(I_, B_), 256>>>(z, zm);
    k_reduce <<<B_, 256>>>(0);
    k_linear2<<<(B_ * I_) / 16, 256>>>(V, W2, b2);
    k_reduce <<<B_, 256>>>(1);
    k_final  <<<(B_ * I_ * C_) / 256, 256>>>(out);
}

// round 13
// speedup vs baseline: 1.0501x; 1.0150x over previous
#include <cuda_runtime.h>
#include <math.h>

#define B_ 4
#define I_ 512
#define K_ 512
#define C_ 64
#define EPS_LN 1e-5f

// -------- scratch (device globals; allocation is forbidden) --------
__device__ float   g_Qa[B_ * K_ * C_];      // Q @ W1^T + b1
__device__ float   g_R [B_ * K_ * C_];      // Qa / D
__device__ float   g_Va[B_ * I_ * C_];      // contraction result (pre-LN1)
__device__ float   g_Vp[B_ * I_ * C_];      // V + LN1(Va)@W2^T + b2 (pre-LN2)
__device__ double2 g_part1[B_ * I_];        // per-(b,i) {sum,sumsq} of Va
__device__ double2 g_part2[128];            // per-linear2-block {sum,sumsq}

// ---------------------------------------------------------------
// Linear1 (R11-proven, 16 rows/block):
//   Qa[row,c] = b1[c] + sum_j Q[row,j]*W1[c,j]
// ---------------------------------------------------------------
__global__ void __launch_bounds__(256) k_linear1(const float* __restrict__ Q,
                                                 const float* __restrict__ W1,
                                                 const float* __restrict__ b1) {
    __shared__ float Ws[C_][C_ + 1];
    __shared__ float Qs[16][C_];
    int t = threadIdx.x;
    int base = blockIdx.x * 16;
    for (int idx = t; idx < C_ * C_; idx += 256)
        Ws[idx / C_][idx % C_] = W1[idx];
    for (int idx = t; idx < 16 * C_; idx += 256)
        Qs[idx >> 6][idx & 63] = Q[(size_t)(base + (idx >> 6)) * C_ + (idx & 63)];
    __syncthreads();
    int c = t & 63, rg = t >> 6;        // rg in 0..3, rows rg*4..rg*4+3
    float bb = __ldg(&b1[c]);
    float a0 = bb, a1 = bb, a2 = bb, a3 = bb;
#pragma unroll
    for (int j = 0; j < C_; j++) {
        float w = Ws[c][j];
        a0 += Qs[rg * 4 + 0][j] * w;
        a1 += Qs[rg * 4 + 1][j] * w;
        a2 += Qs[rg * 4 + 2][j] * w;
        a3 += Qs[rg * 4 + 3][j] * w;
    }
    g_Qa[(size_t)(base + rg * 4 + 0) * C_ + c] = a0;
    g_Qa[(size_t)(base + rg * 4 + 1) * C_ + c] = a1;
    g_Qa[(size_t)(base + rg * 4 + 2) * C_ + c] = a2;
    g_Qa[(size_t)(base + rg * 4 + 3) * C_ + c] = a3;
}

// ---------------------------------------------------------------
// Deterministic active-index compaction (R2-proven form).
//   WMODE 0 : weight = m + 1e-6            [pass1]
//   WMODE 1 : weight = m * (m + 1e-6)      [pass2]
// ---------------------------------------------------------------
template<int WMODE>
__device__ __forceinline__ int compact_active(const float* __restrict__ mp,
                                              size_t mstride,
                                              int* s_idx, float* s_w,
                                              int* s_cnt, int* s_off) {
    int t = threadIdx.x;
    int lane = t & 31, wid = t >> 5;
    float mv[2]; unsigned bal[2];
#pragma unroll
    for (int q = 0; q < 2; q++) {
        int g = wid + q * 8;
        int i = g * 32 + lane;
        mv[q] = __ldg(&mp[(size_t)i * mstride]);
        bal[q] = __ballot_sync(0xffffffffu, mv[q] != 0.f);
        if (lane == 0) s_cnt[g] = __popc(bal[q]);
    }
    __syncthreads();
    if (t == 0) {
        int acc = 0;
#pragma unroll
        for (int g = 0; g < 16; g++) { s_off[g] = acc; acc += s_cnt[g]; }
        s_off[16] = acc;
    }
    __syncthreads();
#pragma unroll
    for (int q = 0; q < 2; q++) {
        int g = wid + q * 8;
        int i = g * 32 + lane;
        if (mv[q] != 0.f) {
            int pos = s_off[g] + __popc(bal[q] & ((1u << lane) - 1u));
            s_idx[pos] = i;
            s_w[pos] = (WMODE == 0) ? (mv[q] + 1e-6f)
                                    : (mv[q] * (mv[q] + 1e-6f));
        }
    }
    __syncthreads();
    return s_off[16];
}

// ---------------------------------------------------------------
// Pass 1 (R9-proven): per (b,k):
//   D[c] = sum_{active i} exp(z[b,i,k,c]) * (m+1e-6)
//   R[b,k,c] = Qa[b,k,c] / D[c]
// ---------------------------------------------------------------
__global__ void __launch_bounds__(256, 8)
k_pass1(const float* __restrict__ z, const float* __restrict__ zm) {
    int k = blockIdx.x, b = blockIdx.y;
    int t = threadIdx.x;
    __shared__ int    s_idx[I_];
    __shared__ float  s_w[I_];
    __shared__ int    s_cnt[16];
    __shared__ int    s_off[17];
    __shared__ float4 red[16][16];

    const float* mp = zm + (size_t)b * I_ * K_ + k;
    int nact = compact_active<0>(mp, K_, s_idx, s_w, s_cnt, s_off);

    int c4 = t & 15;        // float4 channel group
    int di = t >> 4;        // row lane
    const float4* zb = (const float4*)z
        + (((size_t)b * I_) * K_ + k) * (C_ / 4) + c4;
    const size_t zstride = (size_t)K_ * (C_ / 4);

    float4 acc = make_float4(0.f, 0.f, 0.f, 0.f);
#pragma unroll 4
    for (int j = di; j < nact; j += 16) {
        int i = s_idx[j];
        float w = s_w[j];
        float4 zv = __ldg(&zb[(size_t)i * zstride]);
        acc.x += __expf(zv.x) * w;
        acc.y += __expf(zv.y) * w;
        acc.z += __expf(zv.z) * w;
        acc.w += __expf(zv.w) * w;
    }
    red[di][c4] = acc;
    __syncthreads();
    if (t < 16) {
        float4 D = red[0][t];
#pragma unroll
        for (int r = 1; r < 16; r++) {
            float4 v = red[r][t];
            D.x += v.x; D.y += v.y; D.z += v.z; D.w += v.w;
        }
        size_t off = ((size_t)b * K_ + k) * (C_ / 4) + t;
        float4 qa = ((const float4*)g_Qa)[off];
        float4 R = make_float4(qa.x / D.x, qa.y / D.y,
                               qa.z / D.z, qa.w / D.w);
        ((float4*)g_R)[off] = R;
    }
}

// ---------------------------------------------------------------
// Pass 2 (R9-proven): per (b,i):
//   Va[b,i,c] = sum_{active k} m*(m+1e-6) * exp(z[b,i,k,c]) * R[b,k,c]
// Emits per-row LN1 partials.
// ---------------------------------------------------------------
__global__ void __launch_bounds__(256, 8)
k_pass2(const float* __restrict__ z, const float* __restrict__ zm) {
    int i = blockIdx.x, b = blockIdx.y;
    int t = threadIdx.x;
    __shared__ int    s_idx[K_];
    __shared__ float  s_w[K_];
    __shared__ int    s_cnt[16];
    __shared__ int    s_off[17];
    __shared__ float4 red[16][16];
    __shared__ double sd[16], sd2[16];

    const float* mp = zm + ((size_t)b * I_ + i) * K_;
    int nact = compact_active<1>(mp, 1, s_idx, s_w, s_cnt, s_off);

    int c4 = t & 15;
    int dk = t >> 4;
    const float4* zb = (const float4*)z
        + (((size_t)b * I_ + i) * K_) * (C_ / 4) + c4;
    const float4* Rb = (const float4*)g_R + ((size_t)b * K_) * (C_ / 4) + c4;

    float4 acc = make_float4(0.f, 0.f, 0.f, 0.f);
#pragma unroll 4
    for (int j = dk; j < nact; j += 16) {
        int kk = s_idx[j];
        float w = s_w[j];
        float4 zv = __ldg(&zb[(size_t)kk * (C_ / 4)]);
        float4 Rv = __ldg(&Rb[(size_t)kk * (C_ / 4)]);
        acc.x += w * __expf(zv.x) * Rv.x;
        acc.y += w * __expf(zv.y) * Rv.y;
        acc.z += w * __expf(zv.z) * Rv.z;
        acc.w += w * __expf(zv.w) * Rv.w;
    }
    red[dk][c4] = acc;
    __syncthreads();
    if (t < 16) {
        float4 v = red[0][t];
#pragma unroll
        for (int r = 1; r < 16; r++) {
            float4 u = red[r][t];
            v.x += u.x; v.y += u.y; v.z += u.z; v.w += u.w;
        }
        ((float4*)g_Va)[((size_t)b * I_ + i) * (C_ / 4) + t] = v;
        sd [t] = (double)v.x + (double)v.y + (double)v.z + (double)v.w;
        sd2[t] = (double)v.x * v.x + (double)v.y * v.y
               + (double)v.z * v.z + (double)v.w * v.w;
    }
    __syncthreads();
    if (t == 0) {
        double s = 0.0, s2 = 0.0;
#pragma unroll
        for (int r = 0; r < 16; r++) { s += sd[r]; s2 += sd2[r]; }
        g_part1[(size_t)b * I_ + i] = make_double2(s, s2);
    }
}

// ---------------------------------------------------------------
// Linear2 (16 rows/block + inline LN1-stat reduce):
//   every block independently reduces its batch's 512 partials
//   (fixed order -> identical result in every block), then
//   Vp = V + LN1(Va)@W2^T + b2. Emits per-block LN2 partials.
// ---------------------------------------------------------------
__global__ void __launch_bounds__(256) k_linear2(const float* __restrict__ V,
                                                 const float* __restrict__ W2,
                                                 const float* __restrict__ b2) {
    __shared__ float  Ws[C_][C_ + 1];
    __shared__ float  Xs[16][C_];
    __shared__ double sh0[256], sh1[256];
    __shared__ float  s_mu, s_rs;
    int t = threadIdx.x;
    int base = blockIdx.x * 16;
    int b = blockIdx.x >> 5;            // 32 blocks per batch

    // inline reduction of this batch's LN1 partials (L2-resident, 8KB)
    {
        const double2* p = g_part1 + (size_t)b * I_;
        double2 v0 = p[t], v1 = p[t + 256];
        sh0[t] = v0.x + v1.x;
        sh1[t] = v0.y + v1.y;
        __syncthreads();
        for (int o = 128; o > 0; o >>= 1) {
            if (t < o) { sh0[t] += sh0[t + o]; sh1[t] += sh1[t + o]; }
            __syncthreads();
        }
        if (t == 0) {
            const double N = (double)(I_ * C_);
            double mu  = sh0[0] / N;
            double var = sh1[0] / N - mu * mu;
            s_mu = (float)mu;
            s_rs = (float)(1.0 / sqrt(var + (double)EPS_LN));
        }
        __syncthreads();
    }
    float mu = s_mu, rs = s_rs;

    for (int idx = t; idx < C_ * C_; idx += 256)
        Ws[idx / C_][idx % C_] = W2[idx];
    for (int idx = t; idx < 16 * C_; idx += 256)
        Xs[idx >> 6][idx & 63] =
            (g_Va[(size_t)(base + (idx >> 6)) * C_ + (idx & 63)] - mu) * rs;
    __syncthreads();
    int c = t & 63, rg = t >> 6;
    float bb = __ldg(&b2[c]);
    float a0 = bb, a1 = bb, a2 = bb, a3 = bb;
#pragma unroll
    for (int j = 0; j < C_; j++) {
        float w = Ws[c][j];
        a0 += Xs[rg * 4 + 0][j] * w;
        a1 += Xs[rg * 4 + 1][j] * w;
        a2 += Xs[rg * 4 + 2][j] * w;
        a3 += Xs[rg * 4 + 3][j] * w;
    }
    double s = 0.0, s2 = 0.0;
    float av[4] = {a0, a1, a2, a3};
#pragma unroll
    for (int q = 0; q < 4; q++) {
        size_t off = (size_t)(base + rg * 4 + q) * C_ + c;
        float v = __ldg(&V[off]) + av[q];
        g_Vp[off] = v;
        s  += (double)v;
        s2 += (double)v * (double)v;
    }
#pragma unroll
    for (int o = 16; o > 0; o >>= 1) {
        s  += __shfl_down_sync(0xffffffffu, s,  o);
        s2 += __shfl_down_sync(0xffffffffu, s2, o);
    }
    int lane = t & 31, wid = t >> 5;
    __syncthreads();                    // re-use sh0/sh1 safely
    if (lane == 0) { sh0[wid] = s; sh1[wid] = s2; }
    __syncthreads();
    if (t == 0) {
        double ts = 0.0, ts2 = 0.0;
#pragma unroll
        for (int w = 0; w < 8; w++) { ts += sh0[w]; ts2 += sh1[w]; }
        g_part2[blockIdx.x] = make_double2(ts, ts2);
    }
}

// ---------------------------------------------------------------
// Final (+ inline LN2-stat reduce): out = (Vp - mean2[b]) * rstd2[b]
// Each block reduces its batch's 32 partials in warp 0 (fixed order).
// ---------------------------------------------------------------
__global__ void __launch_bounds__(256) k_final(float* __restrict__ out) {
    __shared__ float s_mu, s_rs;
    int t = threadIdx.x;
    int b = blockIdx.x >> 7;            // 128 blocks per batch
    if (t < 32) {
        double2 p = g_part2[b * 32 + t];
        double s = p.x, s2 = p.y;
#pragma unroll
        for (int o = 16; o > 0; o >>= 1) {
            s  += __shfl_down_sync(0xffffffffu, s,  o);
            s2 += __shfl_down_sync(0xffffffffu, s2, o);
        }
        if (t == 0) {
            const double N = (double)(I_ * C_);
            double mu  = s / N;
            double var = s2 / N - mu * mu;
            s_mu = (float)mu;
            s_rs = (float)(1.0 / sqrt(var + (double)EPS_LN));
        }
    }
    __syncthreads();
    int idx = blockIdx.x * 256 + t;
    out[idx] = (g_Vp[idx] - s_mu) * s_rs;
}

// ---------------------------------------------------------------
extern "C" void kernel_launch(void* const* d_in, const int* in_sizes, int n_in,
                              void* d_out, int out_size) {
    const float* V  = (const float*)d_in[0];
    const float* Q  = (const float*)d_in[1];
    const float* z  = (const float*)d_in[2];
    const float* zm = (const float*)d_in[3];
    const float* W1 = (const float*)d_in[4];
    const float* b1 = (const float*)d_in[5];
    const float* W2 = (const float*)d_in[6];
    const float* b2 = (const float*)d_in[7];
    float* out = (float*)d_out;

    k_linear1<<<(B_ * K_) / 16, 256>>>(Q, W1, b1);
    k_pass1  <<<dim3(K_, B_), 256>>>(z, zm);
    k_pass2  <<<dim3(I_, B_), 256>>>(z, zm);
    k_linear2<<<(B_ * I_) / 16, 256>>>(V, W2, b2);
    k_final  <<<(B_ * I_ * C_) / 256, 256>>>(out);
}

// round 15
// speedup vs baseline: 1.2206x; 1.1624x over previous
#include <cuda_runtime.h>
#include <math.h>

#define B_ 4
#define I_ 512
#define K_ 512
#define C_ 64
#define EPS_LN 1e-5f

// -------- scratch (device globals; allocation is forbidden) --------
__device__ float   g_Qa[B_ * K_ * C_];      // Q @ W1^T + b1
__device__ float   g_R [B_ * K_ * C_];      // Qa / D
__device__ float   g_Va[B_ * I_ * C_];      // contraction result (pre-LN1)
__device__ float   g_Vp[B_ * I_ * C_];      // V + LN1(Va)@W2^T + b2 (pre-LN2)
__device__ double2 g_part1[B_ * I_];        // per-(b,i) {sum,sumsq} of Va
__device__ double2 g_part2[256];            // per-linear2-block {sum,sumsq}

// ---- L2 evict-first policy (z is streamed once per pass; keep it
// ---- out of L2's working set so R/Va/partials stay resident).
__device__ __forceinline__ unsigned long long mk_evict_first_policy() {
    unsigned long long pol;
    asm("createpolicy.fractional.L2::evict_first.b64 %0, 1.0;" : "=l"(pol));
    return pol;
}
__device__ __forceinline__ float4 ldg_ef4(const float4* p,
                                          unsigned long long pol) {
    float4 v;
    asm("ld.global.nc.L2::cache_hint.v4.f32 {%0,%1,%2,%3}, [%4], %5;"
        : "=f"(v.x), "=f"(v.y), "=f"(v.z), "=f"(v.w) : "l"(p), "l"(pol));
    return v;
}

// ---------------------------------------------------------------
// Linear1 (R11-proven, 16 rows/block):
//   Qa[row,c] = b1[c] + sum_j Q[row,j]*W1[c,j]
// ---------------------------------------------------------------
__global__ void __launch_bounds__(256) k_linear1(const float* __restrict__ Q,
                                                 const float* __restrict__ W1,
                                                 const float* __restrict__ b1) {
    __shared__ float Ws[C_][C_ + 1];
    __shared__ float Qs[16][C_];
    int t = threadIdx.x;
    int base = blockIdx.x * 16;
    for (int idx = t; idx < C_ * C_; idx += 256)
        Ws[idx / C_][idx % C_] = W1[idx];
    for (int idx = t; idx < 16 * C_; idx += 256)
        Qs[idx >> 6][idx & 63] = Q[(size_t)(base + (idx >> 6)) * C_ + (idx & 63)];
    __syncthreads();
    int c = t & 63, rg = t >> 6;        // rg in 0..3, rows rg*4..rg*4+3
    float bb = __ldg(&b1[c]);
    float a0 = bb, a1 = bb, a2 = bb, a3 = bb;
#pragma unroll
    for (int j = 0; j < C_; j++) {
        float w = Ws[c][j];
        a0 += Qs[rg * 4 + 0][j] * w;
        a1 += Qs[rg * 4 + 1][j] * w;
        a2 += Qs[rg * 4 + 2][j] * w;
        a3 += Qs[rg * 4 + 3][j] * w;
    }
    g_Qa[(size_t)(base + rg * 4 + 0) * C_ + c] = a0;
    g_Qa[(size_t)(base + rg * 4 + 1) * C_ + c] = a1;
    g_Qa[(size_t)(base + rg * 4 + 2) * C_ + c] = a2;
    g_Qa[(size_t)(base + rg * 4 + 3) * C_ + c] = a3;
}

// ---------------------------------------------------------------
// Deterministic active-index compaction (R2-proven form).
//   WMODE 0 : weight = m + 1e-6            [pass1]
//   WMODE 1 : weight = m * (m + 1e-6)      [pass2]
// ---------------------------------------------------------------
template<int WMODE>
__device__ __forceinline__ int compact_active(const float* __restrict__ mp,
                                              size_t mstride,
                                              int* s_idx, float* s_w,
                                              int* s_cnt, int* s_off) {
    int t = threadIdx.x;
    int lane = t & 31, wid = t >> 5;
    float mv[2]; unsigned bal[2];
#pragma unroll
    for (int q = 0; q < 2; q++) {
        int g = wid + q * 8;
        int i = g * 32 + lane;
        mv[q] = __ldg(&mp[(size_t)i * mstride]);
        bal[q] = __ballot_sync(0xffffffffu, mv[q] != 0.f);
        if (lane == 0) s_cnt[g] = __popc(bal[q]);
    }
    __syncthreads();
    if (t == 0) {
        int acc = 0;
#pragma unroll
        for (int g = 0; g < 16; g++) { s_off[g] = acc; acc += s_cnt[g]; }
        s_off[16] = acc;
    }
    __syncthreads();
#pragma unroll
    for (int q = 0; q < 2; q++) {
        int g = wid + q * 8;
        int i = g * 32 + lane;
        if (mv[q] != 0.f) {
            int pos = s_off[g] + __popc(bal[q] & ((1u << lane) - 1u));
            s_idx[pos] = i;
            s_w[pos] = (WMODE == 0) ? (mv[q] + 1e-6f)
                                    : (mv[q] * (mv[q] + 1e-6f));
        }
    }
    __syncthreads();
    return s_off[16];
}

// ---------------------------------------------------------------
// Pass 1 (R9-proven + evict-first z): per (b,k):
//   D[c] = sum_{active i} exp(z[b,i,k,c]) * (m+1e-6)
//   R[b,k,c] = Qa[b,k,c] / D[c]
// ---------------------------------------------------------------
__global__ void __launch_bounds__(256, 8)
k_pass1(const float* __restrict__ z, const float* __restrict__ zm) {
    int k = blockIdx.x, b = blockIdx.y;
    int t = threadIdx.x;
    __shared__ int    s_idx[I_];
    __shared__ float  s_w[I_];
    __shared__ int    s_cnt[16];
    __shared__ int    s_off[17];
    __shared__ float4 red[16][16];

    const float* mp = zm + (size_t)b * I_ * K_ + k;
    int nact = compact_active<0>(mp, K_, s_idx, s_w, s_cnt, s_off);

    unsigned long long pol = mk_evict_first_policy();
    int c4 = t & 15;        // float4 channel group
    int di = t >> 4;        // row lane
    const float4* zb = (const float4*)z
        + (((size_t)b * I_) * K_ + k) * (C_ / 4) + c4;
    const size_t zstride = (size_t)K_ * (C_ / 4);

    float4 acc = make_float4(0.f, 0.f, 0.f, 0.f);
#pragma unroll 4
    for (int j = di; j < nact; j += 16) {
        int i = s_idx[j];
        float w = s_w[j];
        float4 zv = ldg_ef4(&zb[(size_t)i * zstride], pol);
        acc.x += __expf(zv.x) * w;
        acc.y += __expf(zv.y) * w;
        acc.z += __expf(zv.z) * w;
        acc.w += __expf(zv.w) * w;
    }
    red[di][c4] = acc;
    __syncthreads();
    if (t < 16) {
        float4 D = red[0][t];
#pragma unroll
        for (int r = 1; r < 16; r++) {
            float4 v = red[r][t];
            D.x += v.x; D.y += v.y; D.z += v.z; D.w += v.w;
        }
        size_t off = ((size_t)b * K_ + k) * (C_ / 4) + t;
        float4 qa = ((const float4*)g_Qa)[off];
        float4 R = make_float4(qa.x / D.x, qa.y / D.y,
                               qa.z / D.z, qa.w / D.w);
        ((float4*)g_R)[off] = R;
    }
}

// ---------------------------------------------------------------
// Pass 2 (R9-proven + evict-first z): per (b,i):
//   Va[b,i,c] = sum_{active k} m*(m+1e-6) * exp(z[b,i,k,c]) * R[b,k,c]
// R loads keep default policy -> stay L2-resident now that z no
// longer thrashes the cache.
// ---------------------------------------------------------------
__global__ void __launch_bounds__(256, 8)
k_pass2(const float* __restrict__ z, const float* __restrict__ zm) {
    int i = blockIdx.x, b = blockIdx.y;
    int t = threadIdx.x;
    __shared__ int    s_idx[K_];
    __shared__ float  s_w[K_];
    __shared__ int    s_cnt[16];
    __shared__ int    s_off[17];
    __shared__ float4 red[16][16];
    __shared__ double sd[16], sd2[16];

    const float* mp = zm + ((size_t)b * I_ + i) * K_;
    int nact = compact_active<1>(mp, 1, s_idx, s_w, s_cnt, s_off);

    unsigned long long pol = mk_evict_first_policy();
    int c4 = t & 15;
    int dk = t >> 4;
    const float4* zb = (const float4*)z
        + (((size_t)b * I_ + i) * K_) * (C_ / 4) + c4;
    const float4* Rb = (const float4*)g_R + ((size_t)b * K_) * (C_ / 4) + c4;

    float4 acc = make_float4(0.f, 0.f, 0.f, 0.f);
#pragma unroll 4
    for (int j = dk; j < nact; j += 16) {
        int kk = s_idx[j];
        float w = s_w[j];
        float4 zv = ldg_ef4(&zb[(size_t)kk * (C_ / 4)], pol);
        float4 Rv = __ldg(&Rb[(size_t)kk * (C_ / 4)]);
        acc.x += w * __expf(zv.x) * Rv.x;
        acc.y += w * __expf(zv.y) * Rv.y;
        acc.z += w * __expf(zv.z) * Rv.z;
        acc.w += w * __expf(zv.w) * Rv.w;
    }
    red[dk][c4] = acc;
    __syncthreads();
    if (t < 16) {
        float4 v = red[0][t];
#pragma unroll
        for (int r = 1; r < 16; r++) {
            float4 u = red[r][t];
            v.x += u.x; v.y += u.y; v.z += u.z; v.w += u.w;
        }
        ((float4*)g_Va)[((size_t)b * I_ + i) * (C_ / 4) + t] = v;
        sd [t] = (double)v.x + (double)v.y + (double)v.z + (double)v.w;
        sd2[t] = (double)v.x * v.x + (double)v.y * v.y
               + (double)v.z * v.z + (double)v.w * v.w;
    }
    __syncthreads();
    if (t == 0) {
        double s = 0.0, s2 = 0.0;
#pragma unroll
        for (int r = 0; r < 16; r++) { s += sd[r]; s2 += sd2[r]; }
        g_part1[(size_t)b * I_ + i] = make_double2(s, s2);
    }
}

// ---------------------------------------------------------------
// Linear2 (8 rows/block, grid 256, shuffle-based stats):
//   every block redundantly reduces its batch's 512 LN1 partials
//   via warp shuffles (2 barriers total, fixed order), then
//   Vp = V + LN1(Va)@W2^T + b2. Emits per-block LN2 partials.
// ---------------------------------------------------------------
__global__ void __launch_bounds__(256) k_linear2(const float* __restrict__ V,
                                                 const float* __restrict__ W2,
                                                 const float* __restrict__ b2) {
    __shared__ float  Ws[C_][C_ + 1];
    __shared__ float  Xs[8][C_];
    __shared__ double swp[8][2];
    __shared__ float  s_mu, s_rs;
    int t = threadIdx.x;
    int lane = t & 31, wid = t >> 5;
    int base = blockIdx.x * 8;
    int b = blockIdx.x >> 6;            // 64 blocks per batch

    // inline LN1-stat reduce: 512 partials, 2 per thread, shuffles only
    {
        const double2* p = g_part1 + (size_t)b * I_;
        double2 v0 = p[t], v1 = p[t + 256];
        double s = v0.x + v1.x, s2 = v0.y + v1.y;
#pragma unroll
        for (int o = 16; o > 0; o >>= 1) {
            s  += __shfl_down_sync(0xffffffffu, s,  o);
            s2 += __shfl_down_sync(0xffffffffu, s2, o);
        }
        if (lane == 0) { swp[wid][0] = s; swp[wid][1] = s2; }
        __syncthreads();
        if (t == 0) {
            double ts = 0.0, ts2 = 0.0;
#pragma unroll
            for (int w = 0; w < 8; w++) { ts += swp[w][0]; ts2 += swp[w][1]; }
            const double N = (double)(I_ * C_);
            double mu  = ts / N;
            double var = ts2 / N - mu * mu;
            s_mu = (float)mu;
            s_rs = (float)(1.0 / sqrt(var + (double)EPS_LN));
        }
    }

    for (int idx = t; idx < C_ * C_; idx += 256)
        Ws[idx / C_][idx % C_] = W2[idx];
    // Xs needs s_mu: the __syncthreads below orders it after t==0's write
    __syncthreads();
    float mu = s_mu, rs = s_rs;
    for (int idx = t; idx < 8 * C_; idx += 256)
        Xs[idx >> 6][idx & 63] =
            (g_Va[(size_t)(base + (idx >> 6)) * C_ + (idx & 63)] - mu) * rs;
    __syncthreads();
    int c = t & 63, rg = t >> 6;        // rows rg*2, rg*2+1
    float bb = __ldg(&b2[c]);
    float a0 = bb, a1 = bb;
#pragma unroll
    for (int j = 0; j < C_; j++) {
        float w = Ws[c][j];
        a0 += Xs[rg * 2 + 0][j] * w;
        a1 += Xs[rg * 2 + 1][j] * w;
    }
    double s = 0.0, s2 = 0.0;
    float av[2] = {a0, a1};
#pragma unroll
    for (int q = 0; q < 2; q++) {
        size_t off = (size_t)(base + rg * 2 + q) * C_ + c;
        float v = __ldg(&V[off]) + av[q];
        g_Vp[off] = v;
        s  += (double)v;
        s2 += (double)v * (double)v;
    }
#pragma unroll
    for (int o = 16; o > 0; o >>= 1) {
        s  += __shfl_down_sync(0xffffffffu, s,  o);
        s2 += __shfl_down_sync(0xffffffffu, s2, o);
    }
    __syncthreads();                    // re-use swp safely
    if (lane == 0) { swp[wid][0] = s; swp[wid][1] = s2; }
    __syncthreads();
    if (t == 0) {
        double ts = 0.0, ts2 = 0.0;
#pragma unroll
        for (int w = 0; w < 8; w++) { ts += swp[w][0]; ts2 += swp[w][1]; }
        g_part2[blockIdx.x] = make_double2(ts, ts2);
    }
}

// ---------------------------------------------------------------
// Final (+ inline LN2-stat reduce): out = (Vp - mean2[b]) * rstd2[b]
// Warp 0 reduces the batch's 64 partials (fixed order).
// ---------------------------------------------------------------
__global__ void __launch_bounds__(256) k_final(float* __restrict__ out) {
    __shared__ float s_mu, s_rs;
    int t = threadIdx.x;
    int b = blockIdx.x >> 7;            // 128 blocks per batch
    if (t < 32) {
        double2 pa = g_part2[b * 64 + t];
        double2 pb = g_part2[b * 64 + 32 + t];
        double s = pa.x + pb.x, s2 = pa.y + pb.y;
#pragma unroll
        for (int o = 16; o > 0; o >>= 1) {
            s  += __shfl_down_sync(0xffffffffu, s,  o);
            s2 += __shfl_down_sync(0xffffffffu, s2, o);
        }
        if (t == 0) {
            const double N = (double)(I_ * C_);
            double mu  = s / N;
            double var = s2 / N - mu * mu;
            s_mu = (float)mu;
            s_rs = (float)(1.0 / sqrt(var + (double)EPS_LN));
        }
    }
    __syncthreads();
    int idx = blockIdx.x * 256 + t;
    out[idx] = (g_Vp[idx] - s_mu) * s_rs;
}

// ---------------------------------------------------------------
extern "C" void kernel_launch(void* const* d_in, const int* in_sizes, int n_in,
                              void* d_out, int out_size) {
    const float* V  = (const float*)d_in[0];
    const float* Q  = (const float*)d_in[1];
    const float* z  = (const float*)d_in[2];
    const float* zm = (const float*)d_in[3];
    const float* W1 = (const float*)d_in[4];
    const float* b1 = (const float*)d_in[5];
    const float* W2 = (const float*)d_in[6];
    const float* b2 = (const float*)d_in[7];
    float* out = (float*)d_out;

    k_linear1<<<(B_ * K_) / 16, 256>>>(Q, W1, b1);
    k_pass1  <<<dim3(K_, B_), 256>>>(z, zm);
    k_pass2  <<<dim3(I_, B_), 256>>>(z, zm);
    k_linear2<<<(B_ * I_) / 8, 256>>>(V, W2, b2);
    k_final  <<<(B_ * I_ * C_) / 256, 256>>>(out);
}